// round 15
// baseline (speedup 1.0000x reference)
#include <cuda_runtime.h>
#include <cuda_fp16.h>
#include <cstdint>
#include <cstddef>

#define S_LEN 128
#define BATCH 32
#define NIN   512
#define HID   512
#define NLAYER 3
#define VSZ   1536
#define NVOC  50257
#define MROWS (S_LEN*BATCH)
#define LSTM_NCTA 96

// -------- scratch (device globals; fp16 operands, fp32 state) --------
__device__ __half g_xh [MROWS*NIN];
__device__ __half g_Hch[(S_LEN+1)*BATCH*VSZ];
__device__ __half g_yh [MROWS*HID];
__device__ __half g_WhyH[HID*VSZ];
__device__ __half g_WdecH[(size_t)NVOC*HID];
__device__ unsigned g_cnt[NLAYER*S_LEN];

__device__ __forceinline__ float sigm(float x) { return 1.f / (1.f + expf(-x)); }
__device__ __forceinline__ unsigned scvt(const void* p) {
    return (unsigned)__cvta_generic_to_shared(p);
}
__device__ __forceinline__ void cpa16(unsigned d, const void* s, int sz) {
    asm volatile("cp.async.cg.shared.global [%0], [%1], 16, %2;"
                 :: "r"(d), "l"(s), "r"(sz));
}
__device__ __forceinline__ void cpa_commit() { asm volatile("cp.async.commit_group;"); }
__device__ __forceinline__ void ldm4(unsigned& r0, unsigned& r1, unsigned& r2,
                                     unsigned& r3, unsigned a) {
    asm volatile("ldmatrix.sync.aligned.m8n8.x4.shared.b16 {%0,%1,%2,%3}, [%4];"
                 : "=r"(r0), "=r"(r1), "=r"(r2), "=r"(r3) : "r"(a));
}
__device__ __forceinline__ void mma16(float* c, unsigned a0, unsigned a1,
                                      unsigned a2, unsigned a3,
                                      unsigned b0, unsigned b1) {
    asm volatile(
        "mma.sync.aligned.m16n8k16.row.col.f32.f16.f16.f32 "
        "{%0,%1,%2,%3}, {%4,%5,%6,%7}, {%8,%9}, {%0,%1,%2,%3};"
        : "+f"(c[0]), "+f"(c[1]), "+f"(c[2]), "+f"(c[3])
        : "r"(a0), "r"(a1), "r"(a2), "r"(a3), "r"(b0), "r"(b1));
}

// -------- fp16 pre-convert: Why + Wdec --------
__global__ void __launch_bounds__(256) cvt_out(const float4* __restrict__ Why,
                                               const float4* __restrict__ Wdec) {
    const int N1 = HID*VSZ/4;
    const int N2 = (int)((size_t)NVOC*HID/4);
    for (int i = blockIdx.x*256 + threadIdx.x; i < N1 + N2; i += gridDim.x*256) {
        float4 v; __half2* d;
        if (i < N1) { v = Why[i];      d = (__half2*)g_WhyH  + 2*i; }
        else        { v = Wdec[i-N1];  d = (__half2*)g_WdecH + 2*(size_t)(i-N1); }
        d[0] = __floats2half2_rn(v.x, v.y);
        d[1] = __floats2half2_rn(v.z, v.w);
    }
}

// -------- embed gather (fp16) + state init --------
__global__ void __launch_bounds__(256) init_embed(const int* __restrict__ ids,
                                                  const float* __restrict__ emb) {
    int blk = blockIdx.x;
    if (blk < MROWS) {
        int id = ids[blk];
        const float* src = emb + (size_t)id * NIN;
        __half* dst = g_xh + (size_t)blk * NIN;
        for (int k = threadIdx.x; k < NIN; k += 256) dst[k] = __float2half_rn(src[k]);
    } else {
        int z = blk - MROWS;   // zero g_Hch slot 0
        for (int i = threadIdx.x; i < 3072; i += 256)
            g_Hch[(size_t)z*3072 + i] = __ushort_as_half((unsigned short)0);
        if (z == 0) {
            for (int i = threadIdx.x; i < NLAYER*S_LEN; i += 256) g_cnt[i] = 0u;
        }
    }
}

// -------- persistent LSTM: weights resident in smem, dataflow sync --------
// dynamic smem: Bs = 64 rows x LB_LD halves = 197632 B (gate weights, resident)
#define LB_LD 1544
#define LSTM_DSMEM (64*LB_LD*2)

__global__ void __launch_bounds__(256) lstm_wave(
    const float* __restrict__ Wi, const float* __restrict__ Wf,
    const float* __restrict__ Wo, const float* __restrict__ Wg,
    const float* __restrict__ bi, const float* __restrict__ bf,
    const float* __restrict__ bo, const float* __restrict__ bg,
    const float* __restrict__ pci, const float* __restrict__ pcf,
    const float* __restrict__ pco)
{
    extern __shared__ __half Bs[];           // [64][LB_LD]
    __shared__ __half As[2][32*72];
    __shared__ float  Cs[32*64];
    __shared__ float  cst[512];
    __shared__ float  par[112];

    const int cta = blockIdx.x;
    const int j   = cta >> 5;
    const int n0  = (cta & 31) * 16;
    const int tid = threadIdx.x;
    const int warp = tid >> 5, lane = tid & 31;
    const int wm = warp & 1;
    const int wn = warp >> 1;

    const int Keff = (j == 0) ? 1024 : 1536;
    const int nk = Keff >> 6;

    if (tid < 16) {
        int idx = j * HID + n0 + tid;
        par[tid]    = bi[idx];  par[16+tid] = bf[idx];
        par[32+tid] = bo[idx];  par[48+tid] = bg[idx];
        par[64+tid] = pci[idx]; par[80+tid] = pcf[idx];
        par[96+tid] = pco[idx];
    }
    for (int i = tid; i < 512; i += 256) cst[i] = 0.f;

    // ---- one-time weight preload: fp32 global -> fp16 smem (k-compacted) ----
    for (int p = tid*4; p < 64*Keff; p += 1024) {
        int row = p / Keff, k = p - row*Keff;
        int kr = (j == 0 && k >= 512) ? k + 512 : k;
        int gate = row >> 4;
        int n = n0 + (row & 15);
        const float* wsel = (gate == 0) ? Wi : (gate == 1) ? Wf : (gate == 2) ? Wo : Wg;
        float4 v = *(const float4*)(wsel + (size_t)(j*HID + n)*VSZ + kr);
        __half2* d = (__half2*)(Bs + row*LB_LD + k);
        d[0] = __floats2half2_rn(v.x, v.y);
        d[1] = __floats2half2_rn(v.z, v.w);
    }
    __syncthreads();

    for (int t = 0; t < S_LEN; ++t) {
        // ---- dataflow waits (deadline-bounded) ----
        if (tid == 0) {
            if (j > 0) {
                volatile unsigned* c1 = &g_cnt[(j-1)*S_LEN + t];
                unsigned long long dl = clock64() + 2000000000ULL;
                while (*c1 < 32u) { if (clock64() > dl) break; }
            }
            if (t > 0) {
                volatile unsigned* c2 = &g_cnt[j*S_LEN + t - 1];
                unsigned long long dl = clock64() + 2000000000ULL;
                while (*c2 < 32u) { if (clock64() > dl) break; }
            }
            __threadfence();
        }
        __syncthreads();

        float acc[2][4] = {};
        float4 ra;

        auto loadA = [&](int kk) {
            int r = tid >> 3, c8 = tid & 7;
            int kc = kk + c8*8;
            int kr = (j == 0 && kc >= 512) ? kc + 512 : kc;
            const __half* src;
            if (kr < 512)
                src = g_xh + (size_t)(t*BATCH + r)*NIN + kr;
            else if (kr < 1024)
                src = g_Hch + (size_t)((t+1)*BATCH + r)*VSZ + (j-1)*HID + (kr-512);
            else
                src = g_Hch + (size_t)(t*BATCH + r)*VSZ + j*HID + (kr-1024);
            ra = *(const float4*)src;
        };
        auto stsA = [&](int b) {
            int r = tid >> 3, c8 = tid & 7;
            *(float4*)(&As[b][r*72 + c8*8]) = ra;
        };

        loadA(0); stsA(0);
        for (int kt = 0; kt < nk; ++kt) {
            if (kt + 1 < nk) loadA((kt+1)*64);
            __syncthreads();
            const int buf = kt & 1;
#pragma unroll
            for (int ks = 0; ks < 4; ++ks) {
                unsigned a0, a1, a2, a3, b0, b1, b2, b3;
                unsigned aad = scvt(&As[buf][(wm*16 + (lane & 15))*72
                                             + ks*16 + ((lane >> 4) << 3)]);
                ldm4(a0, a1, a2, a3, aad);
                unsigned bad = scvt(&Bs[(wn*16 + ((lane >> 4) << 3) + (lane & 7))*LB_LD
                                        + kt*64 + ks*16 + (((lane >> 3) & 1) << 3)]);
                ldm4(b0, b1, b2, b3, bad);
                mma16(acc[0], a0, a1, a2, a3, b0, b1);
                mma16(acc[1], a0, a1, a2, a3, b2, b3);
            }
            if (kt + 1 < nk) stsA((kt + 1) & 1);
        }
#pragma unroll
        for (int nf = 0; nf < 2; ++nf) {
            int row = wm*16 + (lane >> 2);
            int col = wn*16 + nf*8 + (lane & 3)*2;
            Cs[row*64 + col]       = acc[nf][0];
            Cs[row*64 + col + 1]   = acc[nf][1];
            Cs[(row+8)*64 + col]   = acc[nf][2];
            Cs[(row+8)*64 + col+1] = acc[nf][3];
        }
        __syncthreads();
        for (int p = tid; p < 512; p += 256) {
            int b = p >> 4, hc = p & 15;
            float zi = Cs[b*64 + hc],      zf = Cs[b*64 + 16 + hc];
            float zo = Cs[b*64 + 32 + hc], zg = Cs[b*64 + 48 + hc];
            float c = cst[p];
            float it = sigm(zi + par[hc]    + par[64+hc]*c);
            float ft = sigm(zf + par[16+hc] + par[80+hc]*c);
            float ct = it * tanhf(zg + par[48+hc]) + ft * c;
            float ot = sigm(zo + par[32+hc] + par[96+hc]*c);  // peephole on OLD c
            float h  = ot * tanhf(ct);
            cst[p] = ct;
            g_Hch[(size_t)((t+1)*BATCH + b)*VSZ + j*HID + n0 + hc] = __float2half_rn(h);
        }
        // ---- publish ----
        __threadfence();
        __syncthreads();
        if (tid == 0) atomicAdd(&g_cnt[j*S_LEN + t], 1u);
    }
}

// -------- fp16 tensor GEMM: C[M,N] = A[M,K] @ W[N,K]^T + bias --------
// BM=128, BN=256, BK=32, 4-stage cp.async ring, 8 warps (2m x 4n),
// warp tile 64x64, 1 CTA/SM.
#define G2_LD   40
#define G2_AB   (128*G2_LD*2)          // 10240 B
#define G2_BB   (256*G2_LD*2)          // 20480 B
#define G2_STG  (G2_AB + G2_BB)        // 30720 B
#define G2_SMEM (4*G2_STG)             // 122880 B

__global__ void __launch_bounds__(256, 1)
gemm_h(const __half* __restrict__ A, int lda,
       const __half* __restrict__ W, int ldw,
       const float* __restrict__ bias,
       float* __restrict__ Cf, __half* __restrict__ Ch, int out_half,
       int N, int K)
{
    extern __shared__ char smg[];
    const int tid = threadIdx.x;
    const int warp = tid >> 5, lane = tid & 31;
    const int wm = warp & 1, wn = warp >> 1;
    const int m0 = blockIdx.x * 128;
    const int n0 = blockIdx.y * 256;
    const int nk = K >> 5;

    auto fill = [&](int c, int s) {
        int k0 = c << 5;
        char* sA = smg + s*G2_STG;
        char* sB = sA + G2_AB;
#pragma unroll
        for (int q = 0; q < 2; ++q) {          // A: 128 rows x 4 x16B chunks
            int id = tid + q*256, r = id >> 2, c16 = id & 3;
            cpa16(scvt(sA + (r*G2_LD + c16*8)*2),
                  A + (size_t)(m0 + r)*lda + k0 + c16*8, 16);
        }
#pragma unroll
        for (int q = 0; q < 4; ++q) {          // B: 256 rows x 4 x16B chunks
            int id = tid + q*256, r = id >> 2, c16 = id & 3;
            int n = n0 + r;
            int ncl = (n < N) ? n : 0;
            int sz = (n < N) ? 16 : 0;
            cpa16(scvt(sB + (r*G2_LD + c16*8)*2),
                  W + (size_t)ncl*ldw + k0 + c16*8, sz);
        }
        cpa_commit();
    };

    float acc[4][8][4] = {};
    fill(0, 0); fill(1, 1); fill(2, 2);

    for (int c = 0; c < nk; ++c) {
        asm volatile("cp.async.wait_group 2;" ::: "memory");
        __syncthreads();
        if (c + 3 < nk) fill(c + 3, (c + 3) & 3);
        else cpa_commit();

        const char* sA = smg + (c & 3)*G2_STG;
        const char* sB = sA + G2_AB;
#pragma unroll
        for (int ks = 0; ks < 2; ++ks) {
            unsigned a[4][4], b[8][2];
#pragma unroll
            for (int mf = 0; mf < 4; ++mf) {
                unsigned ad = scvt(sA + ((wm*64 + mf*16 + (lane & 15))*G2_LD
                                         + ks*16 + ((lane >> 4) << 3))*2);
                ldm4(a[mf][0], a[mf][1], a[mf][2], a[mf][3], ad);
            }
#pragma unroll
            for (int np = 0; np < 4; ++np) {
                unsigned bd = scvt(sB + ((wn*64 + np*16 + ((lane >> 4) << 3) + (lane & 7))*G2_LD
                                         + ks*16 + (((lane >> 3) & 1) << 3))*2);
                ldm4(b[2*np][0], b[2*np][1], b[2*np+1][0], b[2*np+1][1], bd);
            }
#pragma unroll
            for (int nf = 0; nf < 8; ++nf)
#pragma unroll
                for (int mf = 0; mf < 4; ++mf)
                    mma16(acc[mf][nf], a[mf][0], a[mf][1], a[mf][2], a[mf][3],
                          b[nf][0], b[nf][1]);
        }
    }

#pragma unroll
    for (int mf = 0; mf < 4; ++mf) {
#pragma unroll
        for (int nf = 0; nf < 8; ++nf) {
            int r  = m0 + wm*64 + mf*16 + (lane >> 2);
            int cn = n0 + wn*64 + nf*8 + (lane & 3)*2;
#pragma unroll
            for (int h2 = 0; h2 < 2; ++h2) {
                int rr = r + h2*8;
                float v0 = acc[mf][nf][2*h2]     + ((cn < N) ? bias[cn] : 0.f);
                float v1 = acc[mf][nf][2*h2 + 1] + ((cn+1 < N) ? bias[cn+1] : 0.f);
                if (out_half) {
                    if (cn < N)     Ch[(size_t)rr*N + cn]     = __float2half_rn(v0);
                    if (cn + 1 < N) Ch[(size_t)rr*N + cn + 1] = __float2half_rn(v1);
                } else {
                    if (cn < N)     Cf[(size_t)rr*N + cn]     = v0;
                    if (cn + 1 < N) Cf[(size_t)rr*N + cn + 1] = v1;
                }
            }
        }
    }
}

extern "C" void kernel_launch(void* const* d_in, const int* in_sizes, int n_in,
                              void* d_out, int out_size) {
    const int*   ids  = (const int*)  d_in[0];
    const float* emb  = (const float*)d_in[1];
    const float* Wi   = (const float*)d_in[2];
    const float* bi   = (const float*)d_in[3];
    const float* Wf   = (const float*)d_in[4];
    const float* bf   = (const float*)d_in[5];
    const float* Wo   = (const float*)d_in[6];
    const float* bo   = (const float*)d_in[7];
    const float* Wg   = (const float*)d_in[8];
    const float* bg   = (const float*)d_in[9];
    const float* pci  = (const float*)d_in[10];
    const float* pcf  = (const float*)d_in[11];
    const float* pco  = (const float*)d_in[12];
    const float* Why  = (const float*)d_in[13];
    const float* bhy  = (const float*)d_in[14];
    const float* Wdec = (const float*)d_in[15];
    const float* bdec = (const float*)d_in[16];
    float* out = (float*)d_out;

    cudaFuncSetAttribute(gemm_h, cudaFuncAttributeMaxDynamicSharedMemorySize, G2_SMEM);
    cudaFuncSetAttribute(lstm_wave, cudaFuncAttributeMaxDynamicSharedMemorySize, LSTM_DSMEM);

    __half *whyh, *wdech, *hch, *yh;
    cudaGetSymbolAddress((void**)&whyh,  g_WhyH);
    cudaGetSymbolAddress((void**)&wdech, g_WdecH);
    cudaGetSymbolAddress((void**)&hch,   g_Hch);
    cudaGetSymbolAddress((void**)&yh,    g_yh);

    cvt_out<<<2048, 256>>>((const float4*)Why, (const float4*)Wdec);
    init_embed<<<MROWS + 16, 256>>>(ids, emb);
    lstm_wave<<<LSTM_NCTA, 256, LSTM_DSMEM>>>(Wi, Wf, Wo, Wg,
                                              bi, bf, bo, bg, pci, pcf, pco);

    {   // y = Hcat @ Why^T + bhy  (M=4096, N=512, K=1536) -> fp16 y
        dim3 grid(MROWS/128, (HID + 255)/256);
        gemm_h<<<grid, 256, G2_SMEM>>>(hch + (size_t)BATCH*VSZ, VSZ,
                                       whyh, VSZ, bhy, nullptr, yh, 1, HID, VSZ);
    }
    {   // logits = y @ Wdec^T + bdec  (M=4096, N=50257, K=512) -> fp32 out
        dim3 grid(MROWS/128, (NVOC + 255)/256);
        gemm_h<<<grid, 256, G2_SMEM>>>(yh, HID, wdech, HID, bdec,
                                       out, nullptr, 0, NVOC, HID);
    }
}

// round 17
// speedup vs baseline: 1.0431x; 1.0431x over previous
#include <cuda_runtime.h>
#include <cuda_fp16.h>
#include <cstdint>
#include <cstddef>

#define S_LEN 128
#define BATCH 32
#define NIN   512
#define HID   512
#define NLAYER 3
#define VSZ   1536
#define NVOC  50257
#define MROWS (S_LEN*BATCH)
#define LSTM_NCTA 96

// -------- scratch (device globals; fp16 operands, fp32 state) --------
__device__ __half g_xh [MROWS*NIN];
__device__ __half g_Hch[(S_LEN+1)*BATCH*VSZ];
__device__ __half g_yh [MROWS*HID];
__device__ __half g_WhyH[HID*VSZ];
__device__ __half g_WdecH[(size_t)NVOC*HID];
__device__ unsigned g_cnt[NLAYER*S_LEN];

__device__ __forceinline__ float sigm(float x) { return 1.f / (1.f + expf(-x)); }
__device__ __forceinline__ unsigned scvt(const void* p) {
    return (unsigned)__cvta_generic_to_shared(p);
}
__device__ __forceinline__ void cpa16(unsigned d, const void* s, int sz) {
    asm volatile("cp.async.cg.shared.global [%0], [%1], 16, %2;"
                 :: "r"(d), "l"(s), "r"(sz));
}
__device__ __forceinline__ void cpa_commit() { asm volatile("cp.async.commit_group;"); }
__device__ __forceinline__ void ldm4(unsigned& r0, unsigned& r1, unsigned& r2,
                                     unsigned& r3, unsigned a) {
    asm volatile("ldmatrix.sync.aligned.m8n8.x4.shared.b16 {%0,%1,%2,%3}, [%4];"
                 : "=r"(r0), "=r"(r1), "=r"(r2), "=r"(r3) : "r"(a));
}
__device__ __forceinline__ void mma16(float* c, unsigned a0, unsigned a1,
                                      unsigned a2, unsigned a3,
                                      unsigned b0, unsigned b1) {
    asm volatile(
        "mma.sync.aligned.m16n8k16.row.col.f32.f16.f16.f32 "
        "{%0,%1,%2,%3}, {%4,%5,%6,%7}, {%8,%9}, {%0,%1,%2,%3};"
        : "+f"(c[0]), "+f"(c[1]), "+f"(c[2]), "+f"(c[3])
        : "r"(a0), "r"(a1), "r"(a2), "r"(a3), "r"(b0), "r"(b1));
}

// -------- fp16 pre-convert: Why + Wdec --------
__global__ void __launch_bounds__(256) cvt_out(const float4* __restrict__ Why,
                                               const float4* __restrict__ Wdec) {
    const int N1 = HID*VSZ/4;
    const int N2 = (int)((size_t)NVOC*HID/4);
    for (int i = blockIdx.x*256 + threadIdx.x; i < N1 + N2; i += gridDim.x*256) {
        float4 v; __half2* d;
        if (i < N1) { v = Why[i];      d = (__half2*)g_WhyH  + 2*i; }
        else        { v = Wdec[i-N1];  d = (__half2*)g_WdecH + 2*(size_t)(i-N1); }
        d[0] = __floats2half2_rn(v.x, v.y);
        d[1] = __floats2half2_rn(v.z, v.w);
    }
}

// -------- embed gather (fp16) + state init --------
__global__ void __launch_bounds__(256) init_embed(const int* __restrict__ ids,
                                                  const float* __restrict__ emb) {
    int blk = blockIdx.x;
    if (blk < MROWS) {
        int id = ids[blk];
        const float* src = emb + (size_t)id * NIN;
        __half* dst = g_xh + (size_t)blk * NIN;
        for (int k = threadIdx.x; k < NIN; k += 256) dst[k] = __float2half_rn(src[k]);
    } else {
        int z = blk - MROWS;   // zero g_Hch slot 0
        for (int i = threadIdx.x; i < 3072; i += 256)
            g_Hch[(size_t)z*3072 + i] = __ushort_as_half((unsigned short)0);
        if (z == 0) {
            for (int i = threadIdx.x; i < NLAYER*S_LEN; i += 256) g_cnt[i] = 0u;
        }
    }
}

// -------- persistent LSTM: weights resident in smem, dataflow sync --------
#define LB_LD 1544
#define LSTM_DSMEM (64*LB_LD*2)

__global__ void __launch_bounds__(256) lstm_wave(
    const float* __restrict__ Wi, const float* __restrict__ Wf,
    const float* __restrict__ Wo, const float* __restrict__ Wg,
    const float* __restrict__ bi, const float* __restrict__ bf,
    const float* __restrict__ bo, const float* __restrict__ bg,
    const float* __restrict__ pci, const float* __restrict__ pcf,
    const float* __restrict__ pco)
{
    extern __shared__ __half Bs[];           // [64][LB_LD]
    __shared__ __half As[2][32*72];
    __shared__ float  Cs[32*64];
    __shared__ float  cst[512];
    __shared__ float  par[112];

    const int cta = blockIdx.x;
    const int j   = cta >> 5;
    const int n0  = (cta & 31) * 16;
    const int tid = threadIdx.x;
    const int warp = tid >> 5, lane = tid & 31;
    const int wm = warp & 1;
    const int wn = warp >> 1;

    const int Keff = (j == 0) ? 1024 : 1536;
    const int nk = Keff >> 6;

    if (tid < 16) {
        int idx = j * HID + n0 + tid;
        par[tid]    = bi[idx];  par[16+tid] = bf[idx];
        par[32+tid] = bo[idx];  par[48+tid] = bg[idx];
        par[64+tid] = pci[idx]; par[80+tid] = pcf[idx];
        par[96+tid] = pco[idx];
    }
    for (int i = tid; i < 512; i += 256) cst[i] = 0.f;

    // ---- one-time weight preload: fp32 global -> fp16 smem (k-compacted) ----
    for (int p = tid*4; p < 64*Keff; p += 1024) {
        int row = p / Keff, k = p - row*Keff;
        int kr = (j == 0 && k >= 512) ? k + 512 : k;
        int gate = row >> 4;
        int n = n0 + (row & 15);
        const float* wsel = (gate == 0) ? Wi : (gate == 1) ? Wf : (gate == 2) ? Wo : Wg;
        float4 v = *(const float4*)(wsel + (size_t)(j*HID + n)*VSZ + kr);
        __half2* d = (__half2*)(Bs + row*LB_LD + k);
        d[0] = __floats2half2_rn(v.x, v.y);
        d[1] = __floats2half2_rn(v.z, v.w);
    }
    __syncthreads();

    for (int t = 0; t < S_LEN; ++t) {
        // ---- dataflow waits (deadline-bounded) ----
        if (tid == 0) {
            if (j > 0) {
                volatile unsigned* c1 = &g_cnt[(j-1)*S_LEN + t];
                unsigned long long dl = clock64() + 2000000000ULL;
                while (*c1 < 32u) { if (clock64() > dl) break; }
            }
            if (t > 0) {
                volatile unsigned* c2 = &g_cnt[j*S_LEN + t - 1];
                unsigned long long dl = clock64() + 2000000000ULL;
                while (*c2 < 32u) { if (clock64() > dl) break; }
            }
            __threadfence();
        }
        __syncthreads();

        float acc[2][4] = {};
        float4 ra;

        auto loadA = [&](int kk) {
            int r = tid >> 3, c8 = tid & 7;
            int kc = kk + c8*8;
            int kr = (j == 0 && kc >= 512) ? kc + 512 : kc;
            const __half* src;
            if (kr < 512)
                src = g_xh + (size_t)(t*BATCH + r)*NIN + kr;
            else if (kr < 1024)
                src = g_Hch + (size_t)((t+1)*BATCH + r)*VSZ + (j-1)*HID + (kr-512);
            else
                src = g_Hch + (size_t)(t*BATCH + r)*VSZ + j*HID + (kr-1024);
            ra = *(const float4*)src;
        };
        auto stsA = [&](int b) {
            int r = tid >> 3, c8 = tid & 7;
            *(float4*)(&As[b][r*72 + c8*8]) = ra;
        };

        loadA(0); stsA(0);
        for (int kt = 0; kt < nk; ++kt) {
            if (kt + 1 < nk) loadA((kt+1)*64);
            __syncthreads();
            const int buf = kt & 1;
#pragma unroll
            for (int ks = 0; ks < 4; ++ks) {
                unsigned a0, a1, a2, a3, b0, b1, b2, b3;
                unsigned aad = scvt(&As[buf][(wm*16 + (lane & 15))*72
                                             + ks*16 + ((lane >> 4) << 3)]);
                ldm4(a0, a1, a2, a3, aad);
                unsigned bad = scvt(&Bs[(wn*16 + ((lane >> 4) << 3) + (lane & 7))*LB_LD
                                        + kt*64 + ks*16 + (((lane >> 3) & 1) << 3)]);
                ldm4(b0, b1, b2, b3, bad);
                mma16(acc[0], a0, a1, a2, a3, b0, b1);
                mma16(acc[1], a0, a1, a2, a3, b2, b3);
            }
            if (kt + 1 < nk) stsA((kt + 1) & 1);
        }
#pragma unroll
        for (int nf = 0; nf < 2; ++nf) {
            int row = wm*16 + (lane >> 2);
            int col = wn*16 + nf*8 + (lane & 3)*2;
            Cs[row*64 + col]       = acc[nf][0];
            Cs[row*64 + col + 1]   = acc[nf][1];
            Cs[(row+8)*64 + col]   = acc[nf][2];
            Cs[(row+8)*64 + col+1] = acc[nf][3];
        }
        __syncthreads();
        for (int p = tid; p < 512; p += 256) {
            int b = p >> 4, hc = p & 15;
            float zi = Cs[b*64 + hc],      zf = Cs[b*64 + 16 + hc];
            float zo = Cs[b*64 + 32 + hc], zg = Cs[b*64 + 48 + hc];
            float c = cst[p];
            float it = sigm(zi + par[hc]    + par[64+hc]*c);
            float ft = sigm(zf + par[16+hc] + par[80+hc]*c);
            float ct = it * tanhf(zg + par[48+hc]) + ft * c;
            float ot = sigm(zo + par[32+hc] + par[96+hc]*c);  // peephole on OLD c
            float h  = ot * tanhf(ct);
            cst[p] = ct;
            g_Hch[(size_t)((t+1)*BATCH + b)*VSZ + j*HID + n0 + hc] = __float2half_rn(h);
        }
        // ---- publish ----
        __threadfence();
        __syncthreads();
        if (tid == 0) atomicAdd(&g_cnt[j*S_LEN + t], 1u);
    }
}

// -------- fp16 tensor GEMM: C[M,N] = A[M,K] @ W[N,K]^T + bias --------
// BM=128, BN=128, BK=32, 4-stage cp.async ring, 8 warps (2m x 4n),
// warp tile 64x32, regs capped for 2 CTAs/SM (16 warps).
#define G3_LD   40
#define G3_AB   (128*G3_LD*2)          // 10240 B
#define G3_BB   (128*G3_LD*2)          // 10240 B
#define G3_STG  (G3_AB + G3_BB)        // 20480 B
#define G3_SMEM (4*G3_STG)             // 81920 B

__global__ void __launch_bounds__(256, 2)
gemm_h(const __half* __restrict__ A, int lda,
       const __half* __restrict__ W, int ldw,
       const float* __restrict__ bias,
       float* __restrict__ Cf, __half* __restrict__ Ch, int out_half,
       int N, int K)
{
    extern __shared__ char smg[];
    const int tid = threadIdx.x;
    const int warp = tid >> 5, lane = tid & 31;
    const int wm = warp & 1, wn = warp >> 1;
    const int m0 = blockIdx.x * 128;
    const int n0 = blockIdx.y * 128;
    const int nk = K >> 5;

    auto fill = [&](int c, int s) {
        int k0 = c << 5;
        char* sA = smg + s*G3_STG;
        char* sB = sA + G3_AB;
#pragma unroll
        for (int q = 0; q < 2; ++q) {          // A: 128 rows x 4 x16B chunks
            int id = tid + q*256, r = id >> 2, c16 = id & 3;
            cpa16(scvt(sA + (r*G3_LD + c16*8)*2),
                  A + (size_t)(m0 + r)*lda + k0 + c16*8, 16);
        }
#pragma unroll
        for (int q = 0; q < 2; ++q) {          // B: 128 rows x 4 x16B chunks
            int id = tid + q*256, r = id >> 2, c16 = id & 3;
            int n = n0 + r;
            int ncl = (n < N) ? n : 0;
            int sz = (n < N) ? 16 : 0;
            cpa16(scvt(sB + (r*G3_LD + c16*8)*2),
                  W + (size_t)ncl*ldw + k0 + c16*8, sz);
        }
        cpa_commit();
    };

    float acc[4][4][4] = {};
    fill(0, 0); fill(1, 1); fill(2, 2);

    for (int c = 0; c < nk; ++c) {
        asm volatile("cp.async.wait_group 2;" ::: "memory");
        __syncthreads();
        if (c + 3 < nk) fill(c + 3, (c + 3) & 3);
        else cpa_commit();

        const char* sA = smg + (c & 3)*G3_STG;
        const char* sB = sA + G3_AB;
#pragma unroll
        for (int ks = 0; ks < 2; ++ks) {
            unsigned a[4][4], b[4][2];
#pragma unroll
            for (int mf = 0; mf < 4; ++mf) {
                unsigned ad = scvt(sA + ((wm*64 + mf*16 + (lane & 15))*G3_LD
                                         + ks*16 + ((lane >> 4) << 3))*2);
                ldm4(a[mf][0], a[mf][1], a[mf][2], a[mf][3], ad);
            }
#pragma unroll
            for (int np = 0; np < 2; ++np) {
                unsigned bd = scvt(sB + ((wn*32 + np*16 + ((lane >> 4) << 3) + (lane & 7))*G3_LD
                                         + ks*16 + (((lane >> 3) & 1) << 3))*2);
                ldm4(b[2*np][0], b[2*np][1], b[2*np+1][0], b[2*np+1][1], bd);
            }
#pragma unroll
            for (int nf = 0; nf < 4; ++nf)
#pragma unroll
                for (int mf = 0; mf < 4; ++mf)
                    mma16(acc[mf][nf], a[mf][0], a[mf][1], a[mf][2], a[mf][3],
                          b[nf][0], b[nf][1]);
        }
    }

#pragma unroll
    for (int mf = 0; mf < 4; ++mf) {
#pragma unroll
        for (int nf = 0; nf < 4; ++nf) {
            int r  = m0 + wm*64 + mf*16 + (lane >> 2);
            int cn = n0 + wn*32 + nf*8 + (lane & 3)*2;
#pragma unroll
            for (int h2 = 0; h2 < 2; ++h2) {
                int rr = r + h2*8;
                float v0 = acc[mf][nf][2*h2]     + ((cn < N) ? bias[cn] : 0.f);
                float v1 = acc[mf][nf][2*h2 + 1] + ((cn+1 < N) ? bias[cn+1] : 0.f);
                if (out_half) {
                    if (cn < N)     Ch[(size_t)rr*N + cn]     = __float2half_rn(v0);
                    if (cn + 1 < N) Ch[(size_t)rr*N + cn + 1] = __float2half_rn(v1);
                } else {
                    if (cn < N)     Cf[(size_t)rr*N + cn]     = v0;
                    if (cn + 1 < N) Cf[(size_t)rr*N + cn + 1] = v1;
                }
            }
        }
    }
}

extern "C" void kernel_launch(void* const* d_in, const int* in_sizes, int n_in,
                              void* d_out, int out_size) {
    const int*   ids  = (const int*)  d_in[0];
    const float* emb  = (const float*)d_in[1];
    const float* Wi   = (const float*)d_in[2];
    const float* bi   = (const float*)d_in[3];
    const float* Wf   = (const float*)d_in[4];
    const float* bf   = (const float*)d_in[5];
    const float* Wo   = (const float*)d_in[6];
    const float* bo   = (const float*)d_in[7];
    const float* Wg   = (const float*)d_in[8];
    const float* bg   = (const float*)d_in[9];
    const float* pci  = (const float*)d_in[10];
    const float* pcf  = (const float*)d_in[11];
    const float* pco  = (const float*)d_in[12];
    const float* Why  = (const float*)d_in[13];
    const float* bhy  = (const float*)d_in[14];
    const float* Wdec = (const float*)d_in[15];
    const float* bdec = (const float*)d_in[16];
    float* out = (float*)d_out;

    cudaFuncSetAttribute(gemm_h, cudaFuncAttributeMaxDynamicSharedMemorySize, G3_SMEM);
    cudaFuncSetAttribute(lstm_wave, cudaFuncAttributeMaxDynamicSharedMemorySize, LSTM_DSMEM);

    __half *whyh, *wdech, *hch, *yh;
    cudaGetSymbolAddress((void**)&whyh,  g_WhyH);
    cudaGetSymbolAddress((void**)&wdech, g_WdecH);
    cudaGetSymbolAddress((void**)&hch,   g_Hch);
    cudaGetSymbolAddress((void**)&yh,    g_yh);

    cvt_out<<<2048, 256>>>((const float4*)Why, (const float4*)Wdec);
    init_embed<<<MROWS + 16, 256>>>(ids, emb);
    lstm_wave<<<LSTM_NCTA, 256, LSTM_DSMEM>>>(Wi, Wf, Wo, Wg,
                                              bi, bf, bo, bg, pci, pcf, pco);

    {   // y = Hcat @ Why^T + bhy  (M=4096, N=512, K=1536) -> fp16 y
        dim3 grid(MROWS/128, (HID + 127)/128);
        gemm_h<<<grid, 256, G3_SMEM>>>(hch + (size_t)BATCH*VSZ, VSZ,
                                       whyh, VSZ, bhy, nullptr, yh, 1, HID, VSZ);
    }
    {   // logits = y @ Wdec^T + bdec  (M=4096, N=50257, K=512) -> fp32 out
        dim3 grid(MROWS/128, (NVOC + 127)/128);
        gemm_h<<<grid, 256, G3_SMEM>>>(yh, HID, wdech, HID, bdec,
                                       out, nullptr, 0, NVOC, HID);
    }
}